// round 13
// baseline (speedup 1.0000x reference)
#include <cuda_runtime.h>
#include <cuda_fp16.h>
#include <cstdint>

constexpr int MTOT = 65536;        // 4096*16 rows

// ---- scratch (allocation-free rule: device globals) ----
__device__ __half g_xh[(size_t)MTOT * 512];
__device__ __half g_wq[512 * 1536];
__device__ __half g_wo[512 * 512];
__device__ __half g_at[(size_t)MTOT * 512];

__device__ __forceinline__ uint32_t sp(const void* p) {
    return (uint32_t)__cvta_generic_to_shared(p);
}
#define CPA(d, s) asm volatile("cp.async.cg.shared.global [%0],[%1],16;" :: "r"(sp(d)), "l"(s))

#define MMA16816(c, a, b0_, b1_)                                                     \
    asm volatile("mma.sync.aligned.m16n8k16.row.col.f32.f16.f16.f32 "                \
                 "{%0,%1,%2,%3},{%4,%5,%6,%7},{%8,%9},{%0,%1,%2,%3};"                \
                 : "+f"((c)[0]), "+f"((c)[1]), "+f"((c)[2]), "+f"((c)[3])            \
                 : "r"((a)[0]), "r"((a)[1]), "r"((a)[2]), "r"((a)[3]),               \
                   "r"(b0_), "r"(b1_))

#define LDSM4(r, p)                                                                  \
    asm volatile("ldmatrix.sync.aligned.m8n8.x4.shared.b16 {%0,%1,%2,%3},[%4];"      \
                 : "=r"((r)[0]), "=r"((r)[1]), "=r"((r)[2]), "=r"((r)[3])            \
                 : "r"(sp(p)))

#define LDSM4T(r, p)                                                                 \
    asm volatile("ldmatrix.sync.aligned.m8n8.x4.trans.shared.b16 {%0,%1,%2,%3},[%4];"\
                 : "=r"((r)[0]), "=r"((r)[1]), "=r"((r)[2]), "=r"((r)[3])            \
                 : "r"(sp(p)))

// ---------------------------------------------------------------------------
// K0: fp32 -> fp16 conversion of x and both weights
// ---------------------------------------------------------------------------
__global__ void k_convert(const float4* __restrict__ x, const float4* __restrict__ wq,
                          const float4* __restrict__ wo) {
    size_t i = (size_t)blockIdx.x * 256 + threadIdx.x;   // float4 index
    if (i < (size_t)MTOT * 128) {
        float4 v = x[i];
        __half2* d = (__half2*)&g_xh[i * 4];
        d[0] = __floats2half2_rn(v.x, v.y); d[1] = __floats2half2_rn(v.z, v.w);
    }
    if (i < 512 * 384) {
        float4 v = wq[i];
        __half2* d = (__half2*)&g_wq[i * 4];
        d[0] = __floats2half2_rn(v.x, v.y); d[1] = __floats2half2_rn(v.z, v.w);
    }
    if (i < 512 * 128) {
        float4 v = wo[i];
        __half2* d = (__half2*)&g_wo[i * 4];
        d[0] = __floats2half2_rn(v.x, v.y); d[1] = __floats2half2_rn(v.z, v.w);
    }
}

// ---------------------------------------------------------------------------
// K1: FUSED qkv-GEMM + attention. Block = (64 rows = 4 batches) x (one head's
// 192 qkv columns). 256 threads, 8 warps (2m x 4n), warp tile 32x48.
// 3-stage cp.async pipeline, K-slab 64 (8 iters, ONE barrier each).
// Epilogue: frags -> fp16 smem, k softmax over n, per-batch tensor-core
// attention (warps 0-3), write g_at.
// ---------------------------------------------------------------------------
constexpr int FAP = 72;      // A smem pitch (64+8) -> 144B, conflict-free
constexpr int FBP = 200;     // B / attn smem pitch (192+8) -> 400B, conflict-free
constexpr int FUSED_SMEM = (3 * 64 * FAP + 3 * 64 * FBP) * 2;   // 104448 B

__global__ __launch_bounds__(256, 2) void k_qkv_attn(const __half* __restrict__ A,
                                                     const __half* __restrict__ Bw) {
    extern __shared__ __half sh[];
    __half* As = sh;                    // [3][64][FAP]
    __half* Bs = sh + 3 * 64 * FAP;     // [3][64][FBP]
    __half* AT = sh;                    // epilogue reuse: [64][FBP] (25.6KB < 27.6KB)

    const int t = threadIdx.x, lane = t & 31, w = t >> 5;
    const int wm = w >> 2, wn = w & 3;
    const int hcol = blockIdx.x * 64;                 // head column base
    const size_t row0 = (size_t)blockIdx.y * 64;

    float c[2][6][4] = {};

#define FLOAD(st, kt) do {                                                             \
    _Pragma("unroll")                                                                  \
    for (int li = 0; li < 2; ++li) {                                                   \
        const int ca = t + li * 256;               /* 0..511 A chunks */               \
        const int r = ca >> 3, kc = ca & 7;                                            \
        CPA(As + ((st) * 64 + r) * FAP + kc * 8,                                       \
            &A[(row0 + r) * 512 + (kt) * 64 + kc * 8]);                                \
    }                                                                                  \
    _Pragma("unroll")                                                                  \
    for (int li = 0; li < 6; ++li) {                                                   \
        const int cB = t + li * 256;               /* 0..1535 B chunks */              \
        const int kr = cB / 24, nc = cB % 24;                                          \
        CPA(Bs + ((st) * 64 + kr) * FBP + nc * 8,                                      \
            &Bw[(size_t)((kt) * 64 + kr) * 1536 + (nc >> 3) * 512 + hcol               \
                + (nc & 7) * 8]);                                                      \
    }                                                                                  \
    asm volatile("cp.async.commit_group;"); } while (0)

    FLOAD(0, 0);
    FLOAD(1, 1);

    for (int kt = 0; kt < 8; ++kt) {
        if (kt < 7) asm volatile("cp.async.wait_group 1;");
        else        asm volatile("cp.async.wait_group 0;");
        __syncthreads();
        // stage (kt+2)%3 == (kt-1)%3 : consumed at iter kt-1, all warps past barrier
        if (kt + 2 < 8) FLOAD((kt + 2) % 3, kt + 2);
        const int st = kt % 3;

        #pragma unroll
        for (int ks = 0; ks < 4; ++ks) {
            const int k0 = ks * 16;
            uint32_t a[2][4], b[3][4];
            #pragma unroll
            for (int mi = 0; mi < 2; ++mi) {
                const __half* p = As + ((size_t)st * 64 + wm * 32 + mi * 16 + (lane & 15)) * FAP
                                     + k0 + 8 * (lane >> 4);
                LDSM4(a[mi], p);
            }
            #pragma unroll
            for (int nj = 0; nj < 3; ++nj) {
                const __half* p = Bs + ((size_t)st * 64 + k0 + (lane & 15)) * FBP
                                     + wn * 48 + nj * 16 + 8 * (lane >> 4);
                LDSM4T(b[nj], p);
            }
            #pragma unroll
            for (int mi = 0; mi < 2; ++mi)
                #pragma unroll
                for (int ni = 0; ni < 6; ++ni)
                    MMA16816(c[mi][ni], a[mi],
                             b[ni >> 1][(ni & 1) * 2], b[ni >> 1][(ni & 1) * 2 + 1]);
        }
    }
#undef FLOAD

    __syncthreads();                  // all ldsm of pipeline smem done before reuse

    // accumulators -> fp16 smem tile [64][192] (cols: 0-63 q, 64-127 k, 128-191 v)
    {
        const int qr = lane >> 2, qc = lane & 3;
        #pragma unroll
        for (int mi = 0; mi < 2; ++mi)
            #pragma unroll
            for (int ni = 0; ni < 6; ++ni) {
                const int r = wm * 32 + mi * 16 + qr;
                const int cc = wn * 48 + ni * 8 + qc * 2;
                *(__half2*)&AT[r * FBP + cc]       = __floats2half2_rn(c[mi][ni][0], c[mi][ni][1]);
                *(__half2*)&AT[(r + 8) * FBP + cc] = __floats2half2_rn(c[mi][ni][2], c[mi][ni][3]);
            }
    }
    __syncthreads();

    // k softmax over n=16 within each batch: 4 batches x 64 cols = 256 tasks
    {
        const int b = t >> 6, col = t & 63;
        __half* p = &AT[(b * 16) * FBP + 64 + col];
        float v[16], mx = -1e30f;
        #pragma unroll
        for (int n = 0; n < 16; ++n) { v[n] = __half2float(p[n * FBP]); mx = fmaxf(mx, v[n]); }
        float s = 0.f;
        #pragma unroll
        for (int n = 0; n < 16; ++n) { v[n] = __expf(v[n] - mx); s += v[n]; }
        const float inv = 1.f / s;
        #pragma unroll
        for (int n = 0; n < 16; ++n) p[n * FBP] = __float2half(v[n] * inv);
    }
    __syncthreads();

    // attention: warps 0-3, one batch each (16 frames)
    if (w < 4) {
        const __half* qb = &AT[(w * 16) * FBP];
        const __half* kb = qb + 64;
        const __half* vb = qb + 128;

        // q fragments (m16 x k64) + in-register softmax over d
        uint32_t qa[4][4];
        #pragma unroll
        for (int kg = 0; kg < 4; ++kg)
            LDSM4(qa[kg], qb + (lane & 15) * FBP + kg * 16 + 8 * (lane >> 4));

        #pragma unroll
        for (int row = 0; row < 2; ++row) {
            float f[16];
            #pragma unroll
            for (int kg = 0; kg < 4; ++kg) {
                float2 x0 = __half22float2(*(__half2*)&qa[kg][row]);
                float2 x1 = __half22float2(*(__half2*)&qa[kg][row + 2]);
                f[4 * kg]     = x0.x; f[4 * kg + 1] = x0.y;
                f[4 * kg + 2] = x1.x; f[4 * kg + 3] = x1.y;
            }
            float mx = -1e30f;
            #pragma unroll
            for (int j = 0; j < 16; ++j) mx = fmaxf(mx, f[j]);
            mx = fmaxf(mx, __shfl_xor_sync(~0u, mx, 1));
            mx = fmaxf(mx, __shfl_xor_sync(~0u, mx, 2));
            float s = 0.f;
            #pragma unroll
            for (int j = 0; j < 16; ++j) { f[j] = __expf(f[j] - mx); s += f[j]; }
            s += __shfl_xor_sync(~0u, s, 1);
            s += __shfl_xor_sync(~0u, s, 2);
            const float inv = 0.125f / s;          // SCALE folded in
            #pragma unroll
            for (int kg = 0; kg < 4; ++kg) {
                *(__half2*)&qa[kg][row]     = __floats2half2_rn(f[4 * kg] * inv, f[4 * kg + 1] * inv);
                *(__half2*)&qa[kg][row + 2] = __floats2half2_rn(f[4 * kg + 2] * inv, f[4 * kg + 3] * inv);
            }
        }

        // S = q k^T : m16 n16 k64
        float s0[4] = {}, s1[4] = {};
        #pragma unroll
        for (int kg = 0; kg < 4; ++kg) {
            uint32_t kf[4];
            LDSM4(kf, kb + (lane & 15) * FBP + kg * 16 + 8 * (lane >> 4));
            MMA16816(s0, qa[kg], kf[0], kf[2]);
            MMA16816(s1, qa[kg], kf[1], kf[3]);
        }

        // S c-frags -> a-frags (fp16)
        uint32_t sa[4];
        *(__half2*)&sa[0] = __floats2half2_rn(s0[0], s0[1]);
        *(__half2*)&sa[1] = __floats2half2_rn(s0[2], s0[3]);
        *(__half2*)&sa[2] = __floats2half2_rn(s1[0], s1[1]);
        *(__half2*)&sa[3] = __floats2half2_rn(s1[2], s1[3]);

        // O = S V : m16 n64 k16
        float o[8][4] = {};
        #pragma unroll
        for (int eg = 0; eg < 4; ++eg) {
            uint32_t vf[4];
            LDSM4T(vf, vb + (lane & 15) * FBP + eg * 16 + 8 * (lane >> 4));
            MMA16816(o[2 * eg],     sa, vf[0], vf[1]);
            MMA16816(o[2 * eg + 1], sa, vf[2], vf[3]);
        }

        const int r0 = lane >> 2, qc = lane & 3;
        const size_t rowB = row0 + w * 16;
        #pragma unroll
        for (int fi = 0; fi < 8; ++fi) {
            const int col = hcol + fi * 8 + qc * 2;
            *(__half2*)&g_at[(rowB + r0) * 512 + col]     = __floats2half2_rn(o[fi][0], o[fi][1]);
            *(__half2*)&g_at[(rowB + r0 + 8) * 512 + col] = __floats2half2_rn(o[fi][2], o[fi][3]);
        }
    }
}

// ---------------------------------------------------------------------------
// K3: output GEMM. C[M,512] = g_at[M,512] * w_out, fp32 out.
// Block 128x128, 8 warps (2m x 4n), warp tile 64x32.
// 3-stage cp.async pipeline, K-slab 64 (8 iters, ONE barrier each).
// ---------------------------------------------------------------------------
constexpr int APITCH = 72;     // 64 + 8 pad -> 144B rows, conflict-free
constexpr int BPITCH = 136;    // 128 + 8 pad -> 272B rows, conflict-free
constexpr int GEMM_SMEM = (3 * 128 * APITCH + 3 * 64 * BPITCH) * 2;   // 107520 B

__global__ __launch_bounds__(256, 2) void k_gemm(const __half* __restrict__ A,
                                                 const __half* __restrict__ B,
                                                 float* __restrict__ C, int N) {
    extern __shared__ __half smh[];
    __half* As = smh;                       // [3][128][APITCH]
    __half* Bs = smh + 3 * 128 * APITCH;    // [3][64][BPITCH]

    const int t = threadIdx.x, lane = t & 31, w = t >> 5;
    const int wm = w >> 2, wn = w & 3;
    const size_t row0 = (size_t)blockIdx.y * 128;
    const int col0 = blockIdx.x * 128;

    float c[4][4][4] = {};

#define LOADTILE(st, kt) do {                                                          \
    _Pragma("unroll")                                                                  \
    for (int li = 0; li < 4; ++li) {                                                   \
        const int ca = t + li * 256;               /* 0..1023 A chunks */              \
        const int r = ca >> 3, kc = ca & 7;                                            \
        CPA(As + ((st) * 128 + r) * APITCH + kc * 8,                                   \
            &A[(row0 + r) * 512 + (kt) * 64 + kc * 8]);                                \
    }                                                                                  \
    _Pragma("unroll")                                                                  \
    for (int li = 0; li < 4; ++li) {                                                   \
        const int cb = t + li * 256;               /* 0..1023 B chunks */              \
        const int kr = cb >> 4, nc = cb & 15;                                          \
        CPA(Bs + ((st) * 64 + kr) * BPITCH + nc * 8,                                   \
            &B[(size_t)((kt) * 64 + kr) * N + col0 + nc * 8]);                         \
    }                                                                                  \
    asm volatile("cp.async.commit_group;"); } while (0)

    LOADTILE(0, 0);
    LOADTILE(1, 1);

    for (int kt = 0; kt < 8; ++kt) {
        if (kt < 7) asm volatile("cp.async.wait_group 1;");
        else        asm volatile("cp.async.wait_group 0;");
        __syncthreads();
        if (kt + 2 < 8) LOADTILE((kt + 2) % 3, kt + 2);
        const int st = kt % 3;

        #pragma unroll
        for (int ks = 0; ks < 4; ++ks) {
            const int k0 = ks * 16;
            uint32_t a[4][4], b[2][4];
            #pragma unroll
            for (int mi = 0; mi < 4; ++mi) {
                const __half* p = As + ((size_t)st * 128 + wm * 64 + mi * 16 + (lane & 15)) * APITCH
                                     + k0 + 8 * (lane >> 4);
                LDSM4(a[mi], p);
            }
            #pragma unroll
            for (int nj = 0; nj < 2; ++nj) {
                const __half* p = Bs + ((size_t)st * 64 + k0 + (lane & 15)) * BPITCH
                                     + wn * 32 + nj * 16 + 8 * (lane >> 4);
                LDSM4T(b[nj], p);
            }
            #pragma unroll
            for (int mi = 0; mi < 4; ++mi)
                #pragma unroll
                for (int ni = 0; ni < 4; ++ni)
                    MMA16816(c[mi][ni], a[mi],
                             b[ni >> 1][(ni & 1) * 2], b[ni >> 1][(ni & 1) * 2 + 1]);
        }
    }
#undef LOADTILE

    const int qr = lane >> 2, qc = lane & 3;
    #pragma unroll
    for (int mi = 0; mi < 4; ++mi)
        #pragma unroll
        for (int ni = 0; ni < 4; ++ni) {
            const size_t r = row0 + wm * 64 + mi * 16 + qr;
            const int cc = col0 + wn * 32 + ni * 8 + qc * 2;
            *(float2*)&C[r * N + cc]       = make_float2(c[mi][ni][0], c[mi][ni][1]);
            *(float2*)&C[(r + 8) * N + cc] = make_float2(c[mi][ni][2], c[mi][ni][3]);
        }
}

// ---------------------------------------------------------------------------
extern "C" void kernel_launch(void* const* d_in, const int* in_sizes, int n_in,
                              void* d_out, int out_size) {
    const float* x  = (const float*)d_in[0];
    const float* wq = (const float*)d_in[1];
    const float* wo = (const float*)d_in[2];

    void *pxh, *pwq, *pwo, *pat;
    cudaGetSymbolAddress(&pxh, g_xh);
    cudaGetSymbolAddress(&pwq, g_wq);
    cudaGetSymbolAddress(&pwo, g_wo);
    cudaGetSymbolAddress(&pat, g_at);

    cudaFuncSetAttribute(k_qkv_attn, cudaFuncAttributeMaxDynamicSharedMemorySize, FUSED_SMEM);
    cudaFuncSetAttribute(k_gemm, cudaFuncAttributeMaxDynamicSharedMemorySize, GEMM_SMEM);

    k_convert<<<32768, 256>>>((const float4*)x, (const float4*)wq, (const float4*)wo);
    k_qkv_attn<<<dim3(8, 1024), 256, FUSED_SMEM>>>((const __half*)pxh, (const __half*)pwq);
    k_gemm<<<dim3(4, 512), 256, GEMM_SMEM>>>((const __half*)pat, (const __half*)pwo,
                                             (float*)d_out, 512);
}

// round 14
// speedup vs baseline: 1.0141x; 1.0141x over previous
#include <cuda_runtime.h>
#include <cuda_fp16.h>
#include <cstdint>

constexpr int MTOT = 65536;        // 4096*16 rows

// ---- scratch (allocation-free rule: device globals) ----
__device__ __half g_xh[(size_t)MTOT * 512];
__device__ __half g_wq[512 * 1536];
__device__ __half g_wo[512 * 512];
__device__ __half g_at[(size_t)MTOT * 512];

__device__ __forceinline__ uint32_t sp(const void* p) {
    return (uint32_t)__cvta_generic_to_shared(p);
}
#define CPA(d, s) asm volatile("cp.async.cg.shared.global [%0],[%1],16;" :: "r"(sp(d)), "l"(s))

#define MMA16816(c, a, b0_, b1_)                                                     \
    asm volatile("mma.sync.aligned.m16n8k16.row.col.f32.f16.f16.f32 "                \
                 "{%0,%1,%2,%3},{%4,%5,%6,%7},{%8,%9},{%0,%1,%2,%3};"                \
                 : "+f"((c)[0]), "+f"((c)[1]), "+f"((c)[2]), "+f"((c)[3])            \
                 : "r"((a)[0]), "r"((a)[1]), "r"((a)[2]), "r"((a)[3]),               \
                   "r"(b0_), "r"(b1_))

#define LDSM4(r, p)                                                                  \
    asm volatile("ldmatrix.sync.aligned.m8n8.x4.shared.b16 {%0,%1,%2,%3},[%4];"      \
                 : "=r"((r)[0]), "=r"((r)[1]), "=r"((r)[2]), "=r"((r)[3])            \
                 : "r"(sp(p)))

#define LDSM4T(r, p)                                                                 \
    asm volatile("ldmatrix.sync.aligned.m8n8.x4.trans.shared.b16 {%0,%1,%2,%3},[%4];"\
                 : "=r"((r)[0]), "=r"((r)[1]), "=r"((r)[2]), "=r"((r)[3])            \
                 : "r"(sp(p)))

// ---------------------------------------------------------------------------
// K0: fp32 -> fp16 conversion of x and both weights (2 float4 per thread)
// ---------------------------------------------------------------------------
__global__ void k_convert(const float4* __restrict__ x, const float4* __restrict__ wq,
                          const float4* __restrict__ wo) {
    #pragma unroll
    for (int rep = 0; rep < 2; ++rep) {
        size_t i = (size_t)blockIdx.x * 512 + rep * 256 + threadIdx.x;  // float4 idx
        if (i < (size_t)MTOT * 128) {
            float4 v = x[i];
            __half2* d = (__half2*)&g_xh[i * 4];
            d[0] = __floats2half2_rn(v.x, v.y); d[1] = __floats2half2_rn(v.z, v.w);
        }
        if (i < 512 * 384) {
            float4 v = wq[i];
            __half2* d = (__half2*)&g_wq[i * 4];
            d[0] = __floats2half2_rn(v.x, v.y); d[1] = __floats2half2_rn(v.z, v.w);
        }
        if (i < 512 * 128) {
            float4 v = wo[i];
            __half2* d = (__half2*)&g_wo[i * 4];
            d[0] = __floats2half2_rn(v.x, v.y); d[1] = __floats2half2_rn(v.z, v.w);
        }
    }
}

// ---------------------------------------------------------------------------
// K1: FUSED qkv-GEMM + attention. Block = (64 rows = 4 batches) x (one head's
// 192 qkv columns). 256 threads, 8 warps (2m x 4n), warp tile 32x48.
// 4-stage cp.async pipeline, K-slab 32, precomputed load offsets.
// Epilogue: frags -> fp16 smem, k softmax over n, per-batch tensor-core
// attention split over ALL 8 warps, write g_at.
// ---------------------------------------------------------------------------
constexpr int FAP = 40;      // A smem pitch (32+8)
constexpr int FBP = 200;     // B / attn smem pitch (192+8)
constexpr int FUSED_SMEM = (4 * 64 * FAP + 4 * 32 * FBP) * 2;   // 71680 B

__global__ __launch_bounds__(256, 2) void k_qkv_attn(const __half* __restrict__ A,
                                                     const __half* __restrict__ Bw) {
    extern __shared__ __half sh[];
    __half* As = sh;                    // [4][64][FAP]
    __half* Bs = sh + 4 * 64 * FAP;     // [4][32][FBP]
    __half* AT = sh;                    // epilogue reuse: [64][FBP]

    const int t = threadIdx.x, lane = t & 31, w = t >> 5;
    const int wm = w >> 2, wn = w & 3;
    const int hcol = blockIdx.x * 64;                 // head column base
    const size_t row0 = (size_t)blockIdx.y * 64;

    // ---- precomputed load offsets (hoisted out of the hot loop) ----
    const uint32_t aSm = (uint32_t)((t >> 2) * FAP + (t & 3) * 8);
    const __half*  aGp = A + (row0 + (t >> 2)) * 512 + (t & 3) * 8;
    uint32_t bSm[3];
    const __half* bGp[3];
    #pragma unroll
    for (int j = 0; j < 3; ++j) {
        const int cB = t + j * 256;                   // 0..767
        const int kr = cB / 24, nc = cB % 24;
        bSm[j] = (uint32_t)(kr * FBP + nc * 8);
        bGp[j] = Bw + (size_t)kr * 1536 + (nc >> 3) * 512 + hcol + (nc & 7) * 8;
    }

    float c[2][6][4] = {};

#define FLOAD(st, kt) do {                                                             \
    CPA(As + (st) * (64 * FAP) + aSm, aGp + (kt) * 32);                                \
    _Pragma("unroll")                                                                  \
    for (int j = 0; j < 3; ++j)                                                        \
        CPA(Bs + (st) * (32 * FBP) + bSm[j], bGp[j] + (size_t)(kt) * (32 * 1536));     \
    asm volatile("cp.async.commit_group;"); } while (0)

    FLOAD(0, 0);
    FLOAD(1, 1);
    FLOAD(2, 2);

    for (int kt = 0; kt < 16; ++kt) {
        if (kt < 14)       asm volatile("cp.async.wait_group 2;");
        else if (kt == 14) asm volatile("cp.async.wait_group 1;");
        else               asm volatile("cp.async.wait_group 0;");
        __syncthreads();
        if (kt + 3 < 16) FLOAD((kt + 3) & 3, kt + 3);
        const int st = kt & 3;

        #pragma unroll
        for (int ks = 0; ks < 2; ++ks) {
            const int k0 = ks * 16;
            uint32_t a[2][4], b[3][4];
            #pragma unroll
            for (int mi = 0; mi < 2; ++mi) {
                const __half* p = As + ((size_t)st * 64 + wm * 32 + mi * 16 + (lane & 15)) * FAP
                                     + k0 + 8 * (lane >> 4);
                LDSM4(a[mi], p);
            }
            #pragma unroll
            for (int nj = 0; nj < 3; ++nj) {
                const __half* p = Bs + ((size_t)st * 32 + k0 + (lane & 15)) * FBP
                                     + wn * 48 + nj * 16 + 8 * (lane >> 4);
                LDSM4T(b[nj], p);
            }
            #pragma unroll
            for (int mi = 0; mi < 2; ++mi)
                #pragma unroll
                for (int ni = 0; ni < 6; ++ni)
                    MMA16816(c[mi][ni], a[mi],
                             b[ni >> 1][(ni & 1) * 2], b[ni >> 1][(ni & 1) * 2 + 1]);
        }
    }
#undef FLOAD

    __syncthreads();                  // all ldsm of pipeline smem done before reuse

    // accumulators -> fp16 smem tile [64][192] (cols: 0-63 q, 64-127 k, 128-191 v)
    {
        const int qr = lane >> 2, qc = lane & 3;
        #pragma unroll
        for (int mi = 0; mi < 2; ++mi)
            #pragma unroll
            for (int ni = 0; ni < 6; ++ni) {
                const int r = wm * 32 + mi * 16 + qr;
                const int cc = wn * 48 + ni * 8 + qc * 2;
                *(__half2*)&AT[r * FBP + cc]       = __floats2half2_rn(c[mi][ni][0], c[mi][ni][1]);
                *(__half2*)&AT[(r + 8) * FBP + cc] = __floats2half2_rn(c[mi][ni][2], c[mi][ni][3]);
            }
    }
    __syncthreads();

    // k softmax over n=16 within each batch: 4 batches x 64 cols = 256 tasks
    {
        const int b = t >> 6, col = t & 63;
        __half* p = &AT[(b * 16) * FBP + 64 + col];
        float v[16], mx = -1e30f;
        #pragma unroll
        for (int n = 0; n < 16; ++n) { v[n] = __half2float(p[n * FBP]); mx = fmaxf(mx, v[n]); }
        float s = 0.f;
        #pragma unroll
        for (int n = 0; n < 16; ++n) { v[n] = __expf(v[n] - mx); s += v[n]; }
        const float inv = 1.f / s;
        #pragma unroll
        for (int n = 0; n < 16; ++n) p[n * FBP] = __float2half(v[n] * inv);
    }
    __syncthreads();

    // attention: ALL 8 warps. batch = w&3; column half = w>>2.
    {
        const int b = w & 3, half = w >> 2;
        const __half* qb = &AT[(b * 16) * FBP];
        const __half* kb = qb + 64;
        const __half* vb = qb + 128;

        // q fragments (m16 x k64) + in-register softmax over d
        uint32_t qa[4][4];
        #pragma unroll
        for (int kg = 0; kg < 4; ++kg)
            LDSM4(qa[kg], qb + (lane & 15) * FBP + kg * 16 + 8 * (lane >> 4));

        #pragma unroll
        for (int row = 0; row < 2; ++row) {
            float f[16];
            #pragma unroll
            for (int kg = 0; kg < 4; ++kg) {
                float2 x0 = __half22float2(*(__half2*)&qa[kg][row]);
                float2 x1 = __half22float2(*(__half2*)&qa[kg][row + 2]);
                f[4 * kg]     = x0.x; f[4 * kg + 1] = x0.y;
                f[4 * kg + 2] = x1.x; f[4 * kg + 3] = x1.y;
            }
            float mx = -1e30f;
            #pragma unroll
            for (int j = 0; j < 16; ++j) mx = fmaxf(mx, f[j]);
            mx = fmaxf(mx, __shfl_xor_sync(~0u, mx, 1));
            mx = fmaxf(mx, __shfl_xor_sync(~0u, mx, 2));
            float s = 0.f;
            #pragma unroll
            for (int j = 0; j < 16; ++j) { f[j] = __expf(f[j] - mx); s += f[j]; }
            s += __shfl_xor_sync(~0u, s, 1);
            s += __shfl_xor_sync(~0u, s, 2);
            const float inv = 0.125f / s;          // SCALE folded in
            #pragma unroll
            for (int kg = 0; kg < 4; ++kg) {
                *(__half2*)&qa[kg][row]     = __floats2half2_rn(f[4 * kg] * inv, f[4 * kg + 1] * inv);
                *(__half2*)&qa[kg][row + 2] = __floats2half2_rn(f[4 * kg + 2] * inv, f[4 * kg + 3] * inv);
            }
        }

        // S = q k^T : m16 n16 k64 (duplicated in warp pair; identical values)
        float s0[4] = {}, s1[4] = {};
        #pragma unroll
        for (int kg = 0; kg < 4; ++kg) {
            uint32_t kf[4];
            LDSM4(kf, kb + (lane & 15) * FBP + kg * 16 + 8 * (lane >> 4));
            MMA16816(s0, qa[kg], kf[0], kf[2]);
            MMA16816(s1, qa[kg], kf[1], kf[3]);
        }

        // S c-frags -> a-frags (fp16)
        uint32_t sa[4];
        *(__half2*)&sa[0] = __floats2half2_rn(s0[0], s0[1]);
        *(__half2*)&sa[1] = __floats2half2_rn(s0[2], s0[3]);
        *(__half2*)&sa[2] = __floats2half2_rn(s1[0], s1[1]);
        *(__half2*)&sa[3] = __floats2half2_rn(s1[2], s1[3]);

        // O = S V : this warp covers output cols [half*32, half*32+32)
        float o[4][4] = {};
        #pragma unroll
        for (int e = 0; e < 2; ++e) {
            const int eg = half * 2 + e;
            uint32_t vf[4];
            LDSM4T(vf, vb + (lane & 15) * FBP + eg * 16 + 8 * (lane >> 4));
            MMA16816(o[2 * e],     sa, vf[0], vf[1]);
            MMA16816(o[2 * e + 1], sa, vf[2], vf[3]);
        }

        const int r0 = lane >> 2, qc = lane & 3;
        const size_t rowB = row0 + b * 16;
        #pragma unroll
        for (int e = 0; e < 2; ++e)
            #pragma unroll
            for (int s = 0; s < 2; ++s) {
                const int fi = (half * 2 + e) * 2 + s;
                const int col = hcol + fi * 8 + qc * 2;
                *(__half2*)&g_at[(rowB + r0) * 512 + col] =
                    __floats2half2_rn(o[2 * e + s][0], o[2 * e + s][1]);
                *(__half2*)&g_at[(rowB + r0 + 8) * 512 + col] =
                    __floats2half2_rn(o[2 * e + s][2], o[2 * e + s][3]);
            }
    }
}

// ---------------------------------------------------------------------------
// K3: output GEMM (proven R12 engine, precomputed offsets).
// C[M,512] = g_at[M,512] * w_out, fp32 out. Block 128x128, warp 64x32,
// 4-stage cp.async pipeline, K-slab 32.
// ---------------------------------------------------------------------------
constexpr int APITCH = 40;
constexpr int BPITCH = 136;
constexpr int GEMM_SMEM = (4 * 128 * APITCH + 4 * 32 * BPITCH) * 2;   // 75776 B

__global__ __launch_bounds__(256, 2) void k_gemm(const __half* __restrict__ A,
                                                 const __half* __restrict__ B,
                                                 float* __restrict__ C, int N) {
    extern __shared__ __half smh[];
    __half* As = smh;
    __half* Bs = smh + 4 * 128 * APITCH;

    const int t = threadIdx.x, lane = t & 31, w = t >> 5;
    const int wm = w >> 2, wn = w & 3;
    const size_t row0 = (size_t)blockIdx.y * 128;
    const int col0 = blockIdx.x * 128;

    // precomputed load offsets
    const uint32_t aSm = (uint32_t)((t >> 2) * APITCH + (t & 3) * 8);
    const __half*  aGp = A + (row0 + (t >> 2)) * 512 + (t & 3) * 8;
    const uint32_t bSm = (uint32_t)((t >> 4) * BPITCH + (t & 15) * 8);
    const __half*  bGp = B + (size_t)(t >> 4) * N + col0 + (t & 15) * 8;

    float c[4][4][4] = {};

#define LOADTILE(st, kt) do {                                                          \
    CPA(As + (st) * (128 * APITCH) + aSm, aGp + (kt) * 32);                            \
    CPA(As + (st) * (128 * APITCH) + aSm + 64 * APITCH, aGp + 64 * 512 + (kt) * 32);   \
    CPA(Bs + (st) * (32 * BPITCH) + bSm, bGp + (size_t)(kt) * 32 * N);                 \
    CPA(Bs + (st) * (32 * BPITCH) + bSm + 16 * BPITCH,                                 \
        bGp + (size_t)((kt) * 32 + 16) * N);                                           \
    asm volatile("cp.async.commit_group;"); } while (0)

    LOADTILE(0, 0);
    LOADTILE(1, 1);
    LOADTILE(2, 2);

    for (int kt = 0; kt < 16; ++kt) {
        if (kt < 14)       asm volatile("cp.async.wait_group 2;");
        else if (kt == 14) asm volatile("cp.async.wait_group 1;");
        else               asm volatile("cp.async.wait_group 0;");
        __syncthreads();
        if (kt + 3 < 16) LOADTILE((kt + 3) & 3, kt + 3);
        const int st = kt & 3;

        #pragma unroll
        for (int ks = 0; ks < 2; ++ks) {
            const int k0 = ks * 16;
            uint32_t a[4][4], b[2][4];
            #pragma unroll
            for (int mi = 0; mi < 4; ++mi) {
                const __half* p = As + ((size_t)st * 128 + wm * 64 + mi * 16 + (lane & 15)) * APITCH
                                     + k0 + 8 * (lane >> 4);
                LDSM4(a[mi], p);
            }
            #pragma unroll
            for (int nj = 0; nj < 2; ++nj) {
                const __half* p = Bs + ((size_t)st * 32 + k0 + (lane & 15)) * BPITCH
                                     + wn * 32 + nj * 16 + 8 * (lane >> 4);
                LDSM4T(b[nj], p);
            }
            #pragma unroll
            for (int mi = 0; mi < 4; ++mi)
                #pragma unroll
                for (int ni = 0; ni < 4; ++ni)
                    MMA16816(c[mi][ni], a[mi],
                             b[ni >> 1][(ni & 1) * 2], b[ni >> 1][(ni & 1) * 2 + 1]);
        }
    }
#undef LOADTILE

    const int qr = lane >> 2, qc = lane & 3;
    #pragma unroll
    for (int mi = 0; mi < 4; ++mi)
        #pragma unroll
        for (int ni = 0; ni < 4; ++ni) {
            const size_t r = row0 + wm * 64 + mi * 16 + qr;
            const int cc = col0 + wn * 32 + ni * 8 + qc * 2;
            *(float2*)&C[r * N + cc]       = make_float2(c[mi][ni][0], c[mi][ni][1]);
            *(float2*)&C[(r + 8) * N + cc] = make_float2(c[mi][ni][2], c[mi][ni][3]);
        }
}

// ---------------------------------------------------------------------------
extern "C" void kernel_launch(void* const* d_in, const int* in_sizes, int n_in,
                              void* d_out, int out_size) {
    const float* x  = (const float*)d_in[0];
    const float* wq = (const float*)d_in[1];
    const float* wo = (const float*)d_in[2];

    void *pxh, *pwq, *pwo, *pat;
    cudaGetSymbolAddress(&pxh, g_xh);
    cudaGetSymbolAddress(&pwq, g_wq);
    cudaGetSymbolAddress(&pwo, g_wo);
    cudaGetSymbolAddress(&pat, g_at);

    cudaFuncSetAttribute(k_qkv_attn, cudaFuncAttributeMaxDynamicSharedMemorySize, FUSED_SMEM);
    cudaFuncSetAttribute(k_gemm, cudaFuncAttributeMaxDynamicSharedMemorySize, GEMM_SMEM);

    k_convert<<<16384, 256>>>((const float4*)x, (const float4*)wq, (const float4*)wo);
    k_qkv_attn<<<dim3(8, 1024), 256, FUSED_SMEM>>>((const __half*)pxh, (const __half*)pwq);
    k_gemm<<<dim3(4, 512), 256, GEMM_SMEM>>>((const __half*)pat, (const __half*)pwo,
                                             (float*)d_out, 512);
}